// round 2
// baseline (speedup 1.0000x reference)
#include <cuda_runtime.h>

#define HH    136
#define WWW   200
#define HW    (HH*WWW)
#define OH    272
#define OW    400
#define NIMG  8
#define NINST 512
#define NPAR  169
#define TB    128

typedef unsigned long long u64;

// scratch (device globals: allocation-free rule)
__device__ float g_featsT[(size_t)NIMG * HH * 8 * WWW];   // [im][y][c][x]
__device__ float g_part[NINST * 8 * 3];                   // per-(inst,band) partial sums

__constant__ float c_soi[6] = {64.f, 128.f, 256.f, 512.f, 1024.f, 2048.f};

// ---------- packed f32x2 helpers ----------
__device__ __forceinline__ u64 pk(float lo, float hi) {
    u64 r; asm("mov.b64 %0, {%1,%2};" : "=l"(r) : "f"(lo), "f"(hi)); return r;
}
__device__ __forceinline__ void upk(u64 v, float& lo, float& hi) {
    asm("mov.b64 {%0,%1}, %2;" : "=f"(lo), "=f"(hi) : "l"(v));
}
__device__ __forceinline__ u64 fma2(u64 a, u64 b, u64 c) {
    u64 d; asm("fma.rn.f32x2 %0, %1, %2, %3;" : "=l"(d) : "l"(a), "l"(b), "l"(c)); return d;
}
__device__ __forceinline__ u64 relu2(u64 v) {
    float lo, hi; upk(v, lo, hi);
    lo = fmaxf(lo, 0.f); hi = fmaxf(hi, 0.f);
    return pk(lo, hi);
}

// ---------- kernel 1: transpose feats to channel-last-per-row [im][y][c][x] ----------
__global__ void transpose_feats(const float* __restrict__ mf) {
    int p = blockIdx.x * blockDim.x + threadIdx.x;
    if (p >= NIMG * HW) return;
    int im  = p / HW;
    int pix = p - im * HW;
    int y = pix / WWW;
    int x = pix - y * WWW;
    float v[8];
#pragma unroll
    for (int c = 0; c < 8; c++) v[c] = mf[((size_t)(im * 8 + c)) * HW + pix];
#pragma unroll
    for (int c = 0; c < 8; c++)
        g_featsT[(((size_t)im * HH + y) * 8 + c) * WWW + x] = v[c];
}

// ---------- kernel 2: fused MLP + upsample + sigmoid + dice partials ----------
__global__ void __launch_bounds__(TB) mask_kernel(
    const float* __restrict__ params,
    const float* __restrict__ iloc,
    const float* __restrict__ gt,
    const int*   __restrict__ im_inds,
    const int*   __restrict__ fpn)
{
    const int b   = blockIdx.x;   // band 0..7 (17 input rows each)
    const int n   = blockIdx.y;   // instance
    const int tid = threadIdx.x;

    __shared__ float sw[NPAR];
    __shared__ float sl[18 * WWW];           // band logits
    __shared__ float red[3][TB / 32];

    for (int i = tid; i < NPAR; i += TB) sw[i] = params[n * NPAR + i];
    const int   im   = __ldg(&im_inds[n]);
    const float sinv = 1.f / c_soi[__ldg(&fpn[n])];
    const float locx = __ldg(&iloc[2 * n]);
    const float locy = __ldg(&iloc[2 * n + 1]);
    __syncthreads();

    const int r0      = b * 17;
    const int nrows   = min(18, HH - r0);    // 18, last band 17
    const int nchunks = nrows * 25;          // 8-px chunks per band

    // ---- phase 1: logits ----
    for (int g = tid; g < nchunks; g += TB) {
        const int row = g / 25;
        const int xb  = (g - row * 25) * 8;
        const int y   = r0 + row;
        const float* fb = &g_featsT[(((size_t)im * HH + y) * 8) * WWW + xb];

        u64 acc[8][4];
#pragma unroll
        for (int o = 0; o < 8; o++) {
            u64 bb = pk(sw[152 + o], sw[152 + o]);
#pragma unroll
            for (int p = 0; p < 4; p++) acc[o][p] = bb;
        }
        // channel 0: relx
        {
            u64 xc[4];
#pragma unroll
            for (int p = 0; p < 4; p++) {
                float lo = (locx - (float)(8 * (xb + 2 * p)     + 4)) * sinv;
                float hi = (locx - (float)(8 * (xb + 2 * p + 1) + 4)) * sinv;
                xc[p] = pk(lo, hi);
            }
#pragma unroll
            for (int o = 0; o < 8; o++) {
                u64 w2 = pk(sw[o * 10], sw[o * 10]);
#pragma unroll
                for (int p = 0; p < 4; p++) acc[o][p] = fma2(w2, xc[p], acc[o][p]);
            }
        }
        // channel 1: rely (uniform over chunk)
        {
            float ry = (locy - (float)(8 * y + 4)) * sinv;
            u64 ryv = pk(ry, ry);
#pragma unroll
            for (int o = 0; o < 8; o++) {
                u64 w2 = pk(sw[o * 10 + 1], sw[o * 10 + 1]);
#pragma unroll
                for (int p = 0; p < 4; p++) acc[o][p] = fma2(w2, ryv, acc[o][p]);
            }
        }
        // channels 2..9: feats
#pragma unroll
        for (int c = 0; c < 8; c++) {
            float4 vlo = *(const float4*)(fb + c * WWW);
            float4 vhi = *(const float4*)(fb + c * WWW + 4);
            u64 xc[4];
            xc[0] = pk(vlo.x, vlo.y); xc[1] = pk(vlo.z, vlo.w);
            xc[2] = pk(vhi.x, vhi.y); xc[3] = pk(vhi.z, vhi.w);
#pragma unroll
            for (int o = 0; o < 8; o++) {
                u64 w2 = pk(sw[o * 10 + 2 + c], sw[o * 10 + 2 + c]);
#pragma unroll
                for (int p = 0; p < 4; p++) acc[o][p] = fma2(w2, xc[p], acc[o][p]);
            }
        }
        u64 h[8][4];
#pragma unroll
        for (int o = 0; o < 8; o++)
#pragma unroll
            for (int p = 0; p < 4; p++) h[o][p] = relu2(acc[o][p]);

        // layer 2
        u64 a2[8][4];
#pragma unroll
        for (int o = 0; o < 8; o++) {
            u64 bb = pk(sw[160 + o], sw[160 + o]);
#pragma unroll
            for (int p = 0; p < 4; p++) a2[o][p] = bb;
        }
#pragma unroll
        for (int c = 0; c < 8; c++) {
#pragma unroll
            for (int o = 0; o < 8; o++) {
                u64 w2 = pk(sw[80 + o * 8 + c], sw[80 + o * 8 + c]);
#pragma unroll
                for (int p = 0; p < 4; p++) a2[o][p] = fma2(w2, h[c][p], a2[o][p]);
            }
        }
#pragma unroll
        for (int o = 0; o < 8; o++)
#pragma unroll
            for (int p = 0; p < 4; p++) h[o][p] = relu2(a2[o][p]);

        // layer 3
        u64 outv[4];
        {
            u64 bb = pk(sw[168], sw[168]);
#pragma unroll
            for (int p = 0; p < 4; p++) outv[p] = bb;
        }
#pragma unroll
        for (int c = 0; c < 8; c++) {
            u64 w2 = pk(sw[144 + c], sw[144 + c]);
#pragma unroll
            for (int p = 0; p < 4; p++) outv[p] = fma2(w2, h[c][p], outv[p]);
        }
#pragma unroll
        for (int p = 0; p < 4; p++) {
            float lo, hi; upk(outv[p], lo, hi);
            sl[row * WWW + xb + 2 * p]     = lo;
            sl[row * WWW + xb + 2 * p + 1] = hi;
        }
    }
    __syncthreads();

    // ---- phase 2: upsample + sigmoid + dice partials ----
    const int i_start = (r0 * 271 + 134) / 135;
    const int i_end   = (b == 7) ? OH : ((r0 + 17) * 271 + 134) / 135;
    const int npx     = (i_end - i_start) * OW;
    const float* gtb  = gt + (size_t)n * OH * OW;

    float aI = 0.f, aS = 0.f, aT = 0.f;
    for (int idx = tid; idx < npx; idx += TB) {
        const int irow = idx / OW;
        const int j    = idx - irow * OW;
        const int i    = i_start + irow;

        float fy = (float)i * (135.f / 271.f);
        int   y0 = (int)fy;
        float wy = fy - (float)y0;
        int ly0 = y0 - r0;
        int ly1 = min(y0 + 1, 135) - r0;
        ly0 = max(0, min(ly0, nrows - 1));
        ly1 = max(0, min(ly1, nrows - 1));

        float fx = (float)j * (199.f / 399.f);
        int   x0 = (int)fx;
        float wx = fx - (float)x0;
        int   x1 = min(x0 + 1, 199);

        float t00 = sl[ly0 * WWW + x0], t01 = sl[ly0 * WWW + x1];
        float t10 = sl[ly1 * WWW + x0], t11 = sl[ly1 * WWW + x1];
        float top = t00 + (t01 - t00) * wx;
        float bot = t10 + (t11 - t10) * wx;
        float v   = top + (bot - top) * wy;

        float s = __fdividef(1.f, 1.f + __expf(-v));
        float t = __ldg(&gtb[i * OW + j]);

        aI = fmaf(s, t, aI);
        aS = fmaf(s, s, aS);
        aT += t;                 // t ∈ {0,1} so t*t == t
    }

#pragma unroll
    for (int off = 16; off > 0; off >>= 1) {
        aI += __shfl_down_sync(0xffffffffu, aI, off);
        aS += __shfl_down_sync(0xffffffffu, aS, off);
        aT += __shfl_down_sync(0xffffffffu, aT, off);
    }
    const int wid = tid >> 5, lane = tid & 31;
    if (lane == 0) { red[0][wid] = aI; red[1][wid] = aS; red[2][wid] = aT; }
    __syncthreads();
    if (tid == 0) {
        float I = 0.f, S = 0.f, T = 0.f;
#pragma unroll
        for (int w = 0; w < TB / 32; w++) { I += red[0][w]; S += red[1][w]; T += red[2][w]; }
        float* gp = &g_part[(n * 8 + b) * 3];
        gp[0] = I; gp[1] = S; gp[2] = T;
    }
}

// ---------- kernel 3: finalize dice loss ----------
__global__ void finalize_kernel(float* __restrict__ out) {
    int n = blockIdx.x * blockDim.x + threadIdx.x;
    if (n >= NINST) return;
    float I = 0.f, S = 0.f, T = 0.f;
#pragma unroll
    for (int b = 0; b < 8; b++) {
        const float* gp = &g_part[(n * 8 + b) * 3];
        I += gp[0]; S += gp[1]; T += gp[2];
    }
    out[n] = 1.f - 2.f * I / (S + T + 1e-5f);
}

extern "C" void kernel_launch(void* const* d_in, const int* in_sizes, int n_in,
                              void* d_out, int out_size) {
    const float* mf     = (const float*)d_in[0];
    const float* params = (const float*)d_in[1];
    const float* iloc   = (const float*)d_in[2];
    const float* gt     = (const float*)d_in[3];
    const int*   imi    = (const int*)d_in[4];
    const int*   fpn    = (const int*)d_in[5];
    float*       out    = (float*)d_out;

    transpose_feats<<<(NIMG * HW + 255) / 256, 256>>>(mf);
    dim3 grid(8, NINST);
    mask_kernel<<<grid, TB>>>(params, iloc, gt, imi, fpn);
    finalize_kernel<<<1, NINST>>>(out);
}